// round 8
// baseline (speedup 1.0000x reference)
#include <cuda_runtime.h>
#include <cstddef>

// ============================================================================
// CommNetActor — algebraically collapsed.
//
//   H0 = sigmoid(O @ W_enc + b_enc)                      [B, A, 64]
//   4 comm layers (all LINEAR) + decoder compose into:
//   out[b] = H0[b].flatten() @ M + const                 M: [4096, 32]
//
// Comm layer: H' = H (Wt - Wb/64) + (1/64) J H Wb + 1 b^T    (J = ones(64,64))
// Closure:    E' = E We ; F' = F(We+Wb) + E Wb ; g' = (We+Wb)^T g + b
// Decoder:    M[(a,k),n] = (E Wdec_a)[k][n] + (1/64 F Wsum)[k][n]
//             const = Wsum^T g + b_dec,  Wsum = sum_a Wdec_a
// ============================================================================

#define TPB 256
#define BPC 4            // batches per CTA
#define NBATCH 8192

__device__ float gE[64 * 64];
__device__ float gT[64 * 32];       // (1/64) F @ Wsum
__device__ float gConst[32];
__device__ float gM[4096 * 32];

// ---------------------------------------------------------------------------
// P1: compose the 4 comm layers -> E, F, g; then T = (1/64) F Wsum, const.
// Single CTA, 256 threads. ~3.2M FMA, ~30us — optimization target for later.
// ---------------------------------------------------------------------------
__global__ void p1_compose(const float* __restrict__ W1, const float* __restrict__ b1,
                           const float* __restrict__ W2, const float* __restrict__ b2,
                           const float* __restrict__ W3, const float* __restrict__ b3,
                           const float* __restrict__ W4, const float* __restrict__ b4,
                           const float* __restrict__ Wdec, const float* __restrict__ bdec)
{
    extern __shared__ float sm[];
    float* sE  = sm;             // 4096
    float* sF  = sm + 4096;      // 4096
    float* sWe = sm + 8192;      // 4096
    float* sWb = sm + 12288;     // 4096
    float* sG  = sm + 16384;     // 64

    const int t = threadIdx.x;

    // init: E = I, F = 0, g = 0
#pragma unroll
    for (int c = 0; c < 16; c++) {
        int idx = t + 256 * c;
        sE[idx] = ((idx >> 6) == (idx & 63)) ? 1.0f : 0.0f;
        sF[idx] = 0.0f;
    }
    if (t < 64) sG[t] = 0.0f;
    __syncthreads();

    const float* Ws[4] = {W1, W2, W3, W4};
    const float* bs[4] = {b1, b2, b3, b4};

    const int ti = t >> 5;        // 0..7 -> 8 rows each
    const int tj = t & 31;        // cols tj and tj+32
    const int i0 = ti * 8;

#pragma unroll
    for (int l = 0; l < 4; l++) {
        const float* W = Ws[l];
        // stage We = Wt - Wb/64 and Wb
#pragma unroll
        for (int c = 0; c < 16; c++) {
            int idx = t + 256 * c;
            float wt = W[idx];
            float wb = W[4096 + idx];
            sWe[idx] = wt - wb * (1.0f / 64.0f);
            sWb[idx] = wb;
        }
        __syncthreads();

        float accE[16], accF[16];   // [8 rows][2 cols]
#pragma unroll
        for (int x = 0; x < 16; x++) { accE[x] = 0.0f; accF[x] = 0.0f; }

        for (int k = 0; k < 64; k++) {
            float we0 = sWe[k * 64 + tj];
            float we1 = sWe[k * 64 + tj + 32];
            float wb0 = sWb[k * 64 + tj];
            float wb1 = sWb[k * 64 + tj + 32];
            float ws0 = we0 + wb0, ws1 = we1 + wb1;
#pragma unroll
            for (int r = 0; r < 8; r++) {
                float e = sE[(i0 + r) * 64 + k];
                float f = sF[(i0 + r) * 64 + k];
                accE[r * 2 + 0] += e * we0;
                accE[r * 2 + 1] += e * we1;
                accF[r * 2 + 0] += f * ws0 + e * wb0;
                accF[r * 2 + 1] += f * ws1 + e * wb1;
            }
        }

        float gnew = 0.0f;
        if (t < 64) {
            for (int k = 0; k < 64; k++)
                gnew += sG[k] * (sWe[k * 64 + t] + sWb[k * 64 + t]);
            gnew += bs[l][t];
        }
        __syncthreads();   // all reads of old E/F/g complete

#pragma unroll
        for (int r = 0; r < 8; r++) {
            sE[(i0 + r) * 64 + tj]      = accE[r * 2 + 0];
            sE[(i0 + r) * 64 + tj + 32] = accE[r * 2 + 1];
            sF[(i0 + r) * 64 + tj]      = accF[r * 2 + 0];
            sF[(i0 + r) * 64 + tj + 32] = accF[r * 2 + 1];
        }
        if (t < 64) sG[t] = gnew;
        __syncthreads();
    }

    // Wsum[d][n] = sum_a Wdec[(a*64+d)*32+n]   (reuse sWe: 2048 floats)
#pragma unroll
    for (int c = 0; c < 8; c++) {
        int idx = t + 256 * c;
        float s = 0.0f;
        for (int a = 0; a < 64; a++) s += Wdec[a * 2048 + idx];
        sWe[idx] = s;
    }
    __syncthreads();

    // T[k][n] = (1/64) sum_d F[k][d] Wsum[d][n]
#pragma unroll
    for (int c = 0; c < 8; c++) {
        int idx = t + 256 * c;
        int k = idx >> 5, n = idx & 31;
        float s = 0.0f;
        for (int d = 0; d < 64; d++) s += sF[k * 64 + d] * sWe[d * 32 + n];
        gT[idx] = s * (1.0f / 64.0f);
    }
    if (t < 32) {
        float s = 0.0f;
        for (int d = 0; d < 64; d++) s += sG[d] * sWe[d * 32 + t];
        gConst[t] = s + bdec[t];
    }
#pragma unroll
    for (int c = 0; c < 16; c++) { int idx = t + 256 * c; gE[idx] = sE[idx]; }
}

// ---------------------------------------------------------------------------
// P2: M[(a*64+k), n] = sum_d E[k][d] * Wdec[(a*64+d)][n] + T[k][n]
// One CTA per agent a.
// ---------------------------------------------------------------------------
__global__ void p2_buildM(const float* __restrict__ Wdec)
{
    __shared__ float sWd[2048];   // Wdec_a  [64][32]
    __shared__ float sE2[4096];   // E       [64][64]
    const int a = blockIdx.x;
    const int t = threadIdx.x;

#pragma unroll
    for (int c = 0; c < 8; c++)  sWd[t + 256 * c] = Wdec[a * 2048 + t + 256 * c];
#pragma unroll
    for (int c = 0; c < 16; c++) sE2[t + 256 * c] = gE[t + 256 * c];
    __syncthreads();

#pragma unroll
    for (int c = 0; c < 8; c++) {
        int idx = t + 256 * c;
        int k = idx >> 5, n = idx & 31;
        float acc = gT[idx];
#pragma unroll 8
        for (int d = 0; d < 64; d++)
            acc += sE2[k * 64 + d] * sWd[d * 32 + n];
        gM[a * 2048 + idx] = acc;
    }
}

// ---------------------------------------------------------------------------
// Main fused kernel: encoder GEMM + sigmoid + decoder reduction.
// CTA = 4 batches (256 rows). 2 encoder passes of 128 rows (2 batches),
// 8x4 per-thread register tile; H kept in smem; decoder reuses each M
// element across the 4 batches.
// ---------------------------------------------------------------------------
__global__ __launch_bounds__(TPB, 1)
void main_kernel(const float* __restrict__ O, const float* __restrict__ Wenc,
                 const float* __restrict__ benc, float* __restrict__ out)
{
    extern __shared__ float sm[];
    float* sW   = sm;                     // 128*64  =  8192 floats
    float* sO   = sm + 8192;              // 128*128 = 16384
    float* sH   = sm + 8192 + 16384;      // 4*4096  = 16384
    float* sB   = sH + 16384;             // 64
    float* sRed = sB + 64;                // 8*4*32  = 1024
    // total 42048 floats = 168192 bytes

    const int t  = threadIdx.x;
    const int bb = blockIdx.x * BPC;

    // stage W_enc [128][64] and bias
    {
        const float4* src = (const float4*)Wenc;
        float4* dst = (float4*)sW;
#pragma unroll
        for (int c = 0; c < 8; c++) dst[t + 256 * c] = src[t + 256 * c];
        if (t < 64) sB[t] = benc[t];
    }

    const int rg = t >> 4;      // 16 row groups of 8 rows
    const int cg = t & 15;      // 16 col groups of 4 cols
    const int r0 = rg * 8;
    const int c0 = cg * 4;

#pragma unroll 1
    for (int p = 0; p < 2; p++) {
        __syncthreads();  // sW/sB ready (p=0); sO free to reuse (p=1)

        // stage O for 2 batches: contiguous 16384 floats
        const float4* osrc = (const float4*)(O + (size_t)(bb + 2 * p) * (64 * 128));
        float4* odst = (float4*)sO;
#pragma unroll
        for (int c = 0; c < 16; c++) odst[t + 256 * c] = osrc[t + 256 * c];
        __syncthreads();

        float acc[8][4];
#pragma unroll
        for (int i = 0; i < 8; i++)
#pragma unroll
            for (int j = 0; j < 4; j++) acc[i][j] = 0.0f;

#pragma unroll 2
        for (int kk = 0; kk < 128; kk += 4) {
            float4 w0 = *(const float4*)&sW[(kk + 0) * 64 + c0];
            float4 w1 = *(const float4*)&sW[(kk + 1) * 64 + c0];
            float4 w2 = *(const float4*)&sW[(kk + 2) * 64 + c0];
            float4 w3 = *(const float4*)&sW[(kk + 3) * 64 + c0];
#pragma unroll
            for (int i = 0; i < 8; i++) {
                float4 o4 = *(const float4*)&sO[(r0 + i) * 128 + kk];
                acc[i][0] += o4.x * w0.x + o4.y * w1.x + o4.z * w2.x + o4.w * w3.x;
                acc[i][1] += o4.x * w0.y + o4.y * w1.y + o4.z * w2.y + o4.w * w3.y;
                acc[i][2] += o4.x * w0.z + o4.y * w1.z + o4.z * w2.z + o4.w * w3.z;
                acc[i][3] += o4.x * w0.w + o4.y * w1.w + o4.z * w2.w + o4.w * w3.w;
            }
        }

        // bias + sigmoid -> sH[batch_local][a*64 + d]
        float bx = sB[c0 + 0], by = sB[c0 + 1], bz = sB[c0 + 2], bw = sB[c0 + 3];
#pragma unroll
        for (int i = 0; i < 8; i++) {
            int row = r0 + i;                 // 0..127
            int bl  = p * 2 + (row >> 6);     // batch local 0..3
            int aa  = row & 63;
            float4 hv;
            hv.x = 1.0f / (1.0f + __expf(-(acc[i][0] + bx)));
            hv.y = 1.0f / (1.0f + __expf(-(acc[i][1] + by)));
            hv.z = 1.0f / (1.0f + __expf(-(acc[i][2] + bz)));
            hv.w = 1.0f / (1.0f + __expf(-(acc[i][3] + bw)));
            *(float4*)&sH[bl * 4096 + aa * 64 + c0] = hv;
        }
    }
    __syncthreads();

    // decoder: out[b] = H0[b] @ M + const. warp w handles rows [w*512, w*512+512),
    // lane n handles output column n; each M element reused for 4 batches.
    const int w = t >> 5;
    const int n = t & 31;
    float dacc0 = 0.0f, dacc1 = 0.0f, dacc2 = 0.0f, dacc3 = 0.0f;
    const float* Mp = gM + (size_t)w * 512 * 32 + n;
    const float* h0 = sH + w * 512;

#pragma unroll 1
    for (int r = 0; r < 512; r += 8) {
        float m[8];
#pragma unroll
        for (int q = 0; q < 8; q++) m[q] = Mp[(r + q) * 32];
#pragma unroll
        for (int q = 0; q < 8; q++) {
            float v0 = h0[r + q];
            float v1 = h0[4096 + r + q];
            float v2 = h0[8192 + r + q];
            float v3 = h0[12288 + r + q];
            dacc0 += v0 * m[q];
            dacc1 += v1 * m[q];
            dacc2 += v2 * m[q];
            dacc3 += v3 * m[q];
        }
    }

    sRed[(w * 4 + 0) * 32 + n] = dacc0;
    sRed[(w * 4 + 1) * 32 + n] = dacc1;
    sRed[(w * 4 + 2) * 32 + n] = dacc2;
    sRed[(w * 4 + 3) * 32 + n] = dacc3;
    __syncthreads();

    if (t < 128) {
        int b  = t >> 5;
        int nn = t & 31;
        float s = gConst[nn];
#pragma unroll
        for (int ww = 0; ww < 8; ww++) s += sRed[(ww * 4 + b) * 32 + nn];
        out[(size_t)(bb + b) * 32 + nn] = s;
    }
}

// ---------------------------------------------------------------------------
extern "C" void kernel_launch(void* const* d_in, const int* in_sizes, int n_in,
                              void* d_out, int out_size)
{
    const float* O    = (const float*)d_in[0];
    const float* Wenc = (const float*)d_in[1];
    const float* benc = (const float*)d_in[2];
    const float* W1   = (const float*)d_in[3];
    const float* b1   = (const float*)d_in[4];
    const float* W2   = (const float*)d_in[5];
    const float* b2   = (const float*)d_in[6];
    const float* W3   = (const float*)d_in[7];
    const float* b3   = (const float*)d_in[8];
    const float* W4   = (const float*)d_in[9];
    const float* b4   = (const float*)d_in[10];
    const float* Wdec = (const float*)d_in[11];
    const float* bdec = (const float*)d_in[12];
    float* out = (float*)d_out;

    // idempotent, cheap; not a stream op so safe under graph capture
    cudaFuncSetAttribute(p1_compose,  cudaFuncAttributeMaxDynamicSharedMemorySize, 16448 * 4);
    cudaFuncSetAttribute(main_kernel, cudaFuncAttributeMaxDynamicSharedMemorySize, 42048 * 4);

    p1_compose<<<1, 256, 16448 * 4>>>(W1, b1, W2, b2, W3, b3, W4, b4, Wdec, bdec);
    p2_buildM<<<64, 256>>>(Wdec);
    main_kernel<<<NBATCH / BPC, TPB, 42048 * 4>>>(O, Wenc, benc, out);
}